// round 13
// baseline (speedup 1.0000x reference)
#include <cuda_runtime.h>
#include <math.h>

// Problem dims
constexpr int B_ = 4;
constexpr int S_ = 2048;
constexpr int D_ = 512;
constexpr size_t NTOT = (size_t)B_ * S_ * D_;

// ---------------- scratch (static __device__, no allocation) ----------------
__device__ float2 g_c1[NTOT];                       // 32 MB complex work (block A)
__device__ float  g_x1[NTOT];                       // x after block A
__device__ float  g_x2[NTOT];                       // x after block B
__device__ float  g_q [NTOT];
__device__ float  g_k [NTOT];
__device__ float  g_v [NTOT];
__device__ float  g_sc[(size_t)B_ * S_ * S_];       // 64 MB scores
__device__ float2 g_twS[S_ / 2];                    // twiddles W_2048^k
__device__ float2 g_twD[D_ / 2];                    // twiddles W_512^k

// ---------------- helpers ----------------
__device__ __forceinline__ float2 cmul(float2 a, float2 b) {
    return make_float2(a.x * b.x - a.y * b.y, a.x * b.y + a.y * b.x);
}

// Stockham auto-sort radix-2 FFT in shared memory.
// tw: N/2 forward twiddles (e^{-2*pi*i*k/N}). INV conjugates (caller scales by 1/N).
// Returns pointer to the buffer holding the result.
template <int N, int NT, bool INV>
__device__ __forceinline__ float2* block_fft(float2* s0, float2* s1, const float2* tw) {
    float2* src = s0;
    float2* dst = s1;
    int n = N, s = 1;
    while (n > 1) {
        __syncthreads();
        #pragma unroll 4
        for (int idx = threadIdx.x; idx < N / 2; idx += NT) {
            int base = idx & ~(s - 1);        // = j*s
            float2 w = tw[base];
            if (INV) w.y = -w.y;
            float2 a = src[idx];
            float2 b = src[idx + N / 2];
            float2 u = make_float2(a.x - b.x, a.y - b.y);
            dst[idx + base]     = make_float2(a.x + b.x, a.y + b.y);
            dst[idx + base + s] = make_float2(u.x * w.x - u.y * w.y,
                                              u.x * w.y + u.y * w.x);
        }
        float2* t = src; src = dst; dst = t;
        n >>= 1; s <<= 1;
    }
    __syncthreads();
    return src;
}

// ---------------- init: twiddle tables (captured, deterministic) ----------------
__global__ void kInit() {
    int i = blockIdx.x * blockDim.x + threadIdx.x;
    if (i < S_ / 2) {
        float sn, cs;
        sincosf(-6.283185307179586476f * (float)i / (float)S_, &sn, &cs);
        g_twS[i] = make_float2(cs, sn);
    }
    if (i < D_ / 2) {
        float sn, cs;
        sincosf(-6.283185307179586476f * (float)i / (float)D_, &sn, &cs);
        g_twD[i] = make_float2(cs, sn);
    }
}

// ---------------- Block A ----------------
// A1: per (b,s) row: DyT(x) -> FFT_D -> g_c1
__global__ void __launch_bounds__(256) kA1(const float* __restrict__ x,
                                           const float* __restrict__ alpha,
                                           const float* __restrict__ w,
                                           const float* __restrict__ bia) {
    __shared__ float2 s0[D_], s1[D_], tw[D_ / 2];
    size_t row = blockIdx.x;
    float al = alpha[0];
    for (int i = threadIdx.x; i < D_ / 2; i += 256) tw[i] = g_twD[i];
    const float* xr = x + row * D_;
    for (int d = threadIdx.x; d < D_; d += 256) {
        float v = tanhf(al * xr[d]) * w[d] + bia[d];
        s0[d] = make_float2(v, 0.0f);
    }
    float2* res = block_fft<D_, 256, false>(s0, s1, tw);
    for (int d = threadIdx.x; d < D_; d += 256) g_c1[row * D_ + d] = res[d];
}

// A2: per (b,d) column of g_c1: FFT_S, elementwise q/(k+eps)*v, IFFT_S, * rtw
__global__ void __launch_bounds__(256) kA2(const float* __restrict__ qr, const float* __restrict__ qi,
                                           const float* __restrict__ kr, const float* __restrict__ ki,
                                           const float* __restrict__ vr, const float* __restrict__ vi,
                                           const float* __restrict__ rtr, const float* __restrict__ rti) {
    __shared__ float2 s0[S_], s1[S_], tw[S_ / 2];
    int b = blockIdx.x / D_;
    int d = blockIdx.x % D_;
    for (int i = threadIdx.x; i < S_ / 2; i += 256) tw[i] = g_twS[i];
    float2 qw = make_float2(qr[d], qi[d]);
    float2 kw = make_float2(kr[d], ki[d]);
    float2 vw = make_float2(vr[d], vi[d]);
    float2 rw = make_float2(rtr[d], rti[d]);
    float2* col = g_c1 + (size_t)b * S_ * D_ + d;
    for (int s = threadIdx.x; s < S_; s += 256) s0[s] = col[(size_t)s * D_];
    float2* F = block_fft<S_, 256, false>(s0, s1, tw);
    for (int i = threadIdx.x; i < S_; i += 256) {
        float2 f = F[i];
        float2 q = cmul(qw, f);
        float2 k = cmul(kw, f);
        float2 v = cmul(vw, f);
        k.x += 1e-12f;
        float inv = 1.0f / (k.x * k.x + k.y * k.y);
        float2 u = make_float2((q.x * k.x + q.y * k.y) * inv,
                               (q.y * k.x - q.x * k.y) * inv);
        F[i] = cmul(u, v);
    }
    float2* other = (F == s0) ? s1 : s0;
    float2* res = block_fft<S_, 256, true>(F, other, tw);
    const float sc = 1.0f / (float)S_;
    for (int i = threadIdx.x; i < S_; i += 256) {
        float2 r = cmul(res[i], rw);
        col[(size_t)i * D_] = make_float2(r.x * sc, r.y * sc);
    }
}

// A3: per (b,s) row: IFFT_D(g_c1).real + x -> g_x1
__global__ void __launch_bounds__(256) kA3(const float* __restrict__ x) {
    __shared__ float2 s0[D_], s1[D_], tw[D_ / 2];
    size_t row = blockIdx.x;
    for (int i = threadIdx.x; i < D_ / 2; i += 256) tw[i] = g_twD[i];
    for (int d = threadIdx.x; d < D_; d += 256) s0[d] = g_c1[row * D_ + d];
    float2* res = block_fft<D_, 256, true>(s0, s1, tw);
    const float sc = 1.0f / (float)D_;
    for (int d = threadIdx.x; d < D_; d += 256)
        g_x1[row * D_ + d] = res[d].x * sc + x[row * D_ + d];
}

// ---------------- Block B: Fourier projections + attention ----------------
// B1: per row: DyT(x1) -> FFT_D -> Xf; q/k/v = IFFT_D(Xf*w).real
__global__ void __launch_bounds__(256) kB1(const float* __restrict__ alpha,
                                           const float* __restrict__ w,
                                           const float* __restrict__ bia,
                                           const float* __restrict__ qr, const float* __restrict__ qi,
                                           const float* __restrict__ kr, const float* __restrict__ ki,
                                           const float* __restrict__ vr, const float* __restrict__ vi) {
    __shared__ float2 s0[D_], s1[D_], sXf[D_], tw[D_ / 2];
    size_t row = blockIdx.x;
    float al = alpha[0];
    for (int i = threadIdx.x; i < D_ / 2; i += 256) tw[i] = g_twD[i];
    for (int d = threadIdx.x; d < D_; d += 256)
        s0[d] = make_float2(tanhf(al * g_x1[row * D_ + d]) * w[d] + bia[d], 0.0f);
    float2* res = block_fft<D_, 256, false>(s0, s1, tw);
    for (int d = threadIdx.x; d < D_; d += 256) sXf[d] = res[d];
    __syncthreads();
    const float sc = 1.0f / (float)D_;
    // q
    for (int d = threadIdx.x; d < D_; d += 256)
        s0[d] = cmul(sXf[d], make_float2(qr[d], qi[d]));
    res = block_fft<D_, 256, true>(s0, s1, tw);
    for (int d = threadIdx.x; d < D_; d += 256) g_q[row * D_ + d] = res[d].x * sc;
    __syncthreads();
    // k
    for (int d = threadIdx.x; d < D_; d += 256)
        s0[d] = cmul(sXf[d], make_float2(kr[d], ki[d]));
    res = block_fft<D_, 256, true>(s0, s1, tw);
    for (int d = threadIdx.x; d < D_; d += 256) g_k[row * D_ + d] = res[d].x * sc;
    __syncthreads();
    // v
    for (int d = threadIdx.x; d < D_; d += 256)
        s0[d] = cmul(sXf[d], make_float2(vr[d], vi[d]));
    res = block_fft<D_, 256, true>(s0, s1, tw);
    for (int d = threadIdx.x; d < D_; d += 256) g_v[row * D_ + d] = res[d].x * sc;
}

// GEMM1: scores[b,m,n] = (1/sqrt(D)) * dot(q[b,m,:], k[b,n,:])
constexpr int BM = 128, BN = 128, BK = 16;

__global__ void __launch_bounds__(256) kGemmQK() {
    __shared__ float As[BK][BM + 4];
    __shared__ float Bs[BK][BN + 4];
    int b = blockIdx.z;
    int m0 = blockIdx.y * BM;
    int n0 = blockIdx.x * BN;
    const float* Q = g_q + (size_t)b * S_ * D_;
    const float* K = g_k + (size_t)b * S_ * D_;
    float acc[8][8] = {};
    int tx = threadIdx.x & 15, ty = threadIdx.x >> 4;
    for (int k0 = 0; k0 < D_; k0 += BK) {
        #pragma unroll
        for (int i = 0; i < 2; i++) {
            int f = threadIdx.x + i * 256;      // 0..511
            int r = f >> 2;                     // row 0..127
            int c4 = (f & 3) * 4;               // col 0,4,8,12
            float4 va = *(const float4*)(Q + (size_t)(m0 + r) * D_ + k0 + c4);
            As[c4 + 0][r] = va.x; As[c4 + 1][r] = va.y;
            As[c4 + 2][r] = va.z; As[c4 + 3][r] = va.w;
            float4 vb = *(const float4*)(K + (size_t)(n0 + r) * D_ + k0 + c4);
            Bs[c4 + 0][r] = vb.x; Bs[c4 + 1][r] = vb.y;
            Bs[c4 + 2][r] = vb.z; Bs[c4 + 3][r] = vb.w;
        }
        __syncthreads();
        #pragma unroll
        for (int kk = 0; kk < BK; kk++) {
            float a[8], bb[8];
            *(float4*)&a[0]  = *(const float4*)&As[kk][ty * 8];
            *(float4*)&a[4]  = *(const float4*)&As[kk][ty * 8 + 4];
            *(float4*)&bb[0] = *(const float4*)&Bs[kk][tx * 8];
            *(float4*)&bb[4] = *(const float4*)&Bs[kk][tx * 8 + 4];
            #pragma unroll
            for (int i = 0; i < 8; i++)
                #pragma unroll
                for (int j = 0; j < 8; j++)
                    acc[i][j] += a[i] * bb[j];
        }
        __syncthreads();
    }
    const float scale = 0.044194173824159216f;  // 1/sqrt(512)
    float* C = g_sc + (size_t)b * S_ * S_;
    #pragma unroll
    for (int i = 0; i < 8; i++) {
        size_t roff = (size_t)(m0 + ty * 8 + i) * S_ + n0 + tx * 8;
        #pragma unroll
        for (int j = 0; j < 8; j += 4) {
            float4 o = make_float4(acc[i][j] * scale, acc[i][j + 1] * scale,
                                   acc[i][j + 2] * scale, acc[i][j + 3] * scale);
            *(float4*)(C + roff + j) = o;
        }
    }
}

// softmax over last axis of g_sc (rows of length S_)
__global__ void __launch_bounds__(256) kSoftmax() {
    __shared__ float red[256];
    size_t row = blockIdx.x;
    float* r = g_sc + row * S_;
    float vals[8];
    float mx = -1e30f;
    #pragma unroll
    for (int i = 0; i < 8; i++) {
        vals[i] = r[threadIdx.x + i * 256];
        mx = fmaxf(mx, vals[i]);
    }
    red[threadIdx.x] = mx;
    __syncthreads();
    for (int off = 128; off > 0; off >>= 1) {
        if (threadIdx.x < off)
            red[threadIdx.x] = fmaxf(red[threadIdx.x], red[threadIdx.x + off]);
        __syncthreads();
    }
    mx = red[0];
    __syncthreads();
    float sum = 0.0f;
    #pragma unroll
    for (int i = 0; i < 8; i++) {
        vals[i] = __expf(vals[i] - mx);
        sum += vals[i];
    }
    red[threadIdx.x] = sum;
    __syncthreads();
    for (int off = 128; off > 0; off >>= 1) {
        if (threadIdx.x < off) red[threadIdx.x] += red[threadIdx.x + off];
        __syncthreads();
    }
    float inv = 1.0f / red[0];
    #pragma unroll
    for (int i = 0; i < 8; i++) r[threadIdx.x + i * 256] = vals[i] * inv;
}

// GEMM2: x2[b,m,n] = sum_t P[b,m,t] * V[b,t,n] + x1[b,m,n]
__global__ void __launch_bounds__(256) kGemmPV() {
    __shared__ float As[BK][BM + 4];
    __shared__ float Bs[BK][BN];
    int b = blockIdx.z;
    int m0 = blockIdx.y * BM;
    int n0 = blockIdx.x * BN;
    const float* P = g_sc + (size_t)b * S_ * S_;
    const float* V = g_v + (size_t)b * S_ * D_;
    float acc[8][8] = {};
    int tx = threadIdx.x & 15, ty = threadIdx.x >> 4;
    for (int k0 = 0; k0 < S_; k0 += BK) {
        #pragma unroll
        for (int i = 0; i < 2; i++) {
            int f = threadIdx.x + i * 256;
            int r = f >> 2;
            int c4 = (f & 3) * 4;
            float4 va = *(const float4*)(P + (size_t)(m0 + r) * S_ + k0 + c4);
            As[c4 + 0][r] = va.x; As[c4 + 1][r] = va.y;
            As[c4 + 2][r] = va.z; As[c4 + 3][r] = va.w;
            int rb = f >> 5;               // 0..15
            int cb = (f & 31) * 4;         // 0..124
            *(float4*)&Bs[rb][cb] =
                *(const float4*)(V + (size_t)(k0 + rb) * D_ + n0 + cb);
        }
        __syncthreads();
        #pragma unroll
        for (int kk = 0; kk < BK; kk++) {
            float a[8], bb[8];
            *(float4*)&a[0]  = *(const float4*)&As[kk][ty * 8];
            *(float4*)&a[4]  = *(const float4*)&As[kk][ty * 8 + 4];
            *(float4*)&bb[0] = *(const float4*)&Bs[kk][tx * 8];
            *(float4*)&bb[4] = *(const float4*)&Bs[kk][tx * 8 + 4];
            #pragma unroll
            for (int i = 0; i < 8; i++)
                #pragma unroll
                for (int j = 0; j < 8; j++)
                    acc[i][j] += a[i] * bb[j];
        }
        __syncthreads();
    }
    const float* X1 = g_x1 + (size_t)b * S_ * D_;
    float* X2 = g_x2 + (size_t)b * S_ * D_;
    #pragma unroll
    for (int i = 0; i < 8; i++) {
        size_t roff = (size_t)(m0 + ty * 8 + i) * D_ + n0 + tx * 8;
        #pragma unroll
        for (int j = 0; j < 8; j += 4) {
            float4 rr = *(const float4*)(X1 + roff + j);
            float4 o = make_float4(acc[i][j] + rr.x, acc[i][j + 1] + rr.y,
                                   acc[i][j + 2] + rr.z, acc[i][j + 3] + rr.w);
            *(float4*)(X2 + roff + j) = o;
        }
    }
}

// ---------------- Block C: FFN ----------------
__global__ void __launch_bounds__(256) kC(const float* __restrict__ alpha,
                                          const float* __restrict__ w,
                                          const float* __restrict__ bia,
                                          const float* __restrict__ br,
                                          const float* __restrict__ bi,
                                          float* __restrict__ out) {
    __shared__ float2 s0[D_], s1[D_], tw[D_ / 2];
    size_t row = blockIdx.x;
    float al = alpha[0];
    for (int i = threadIdx.x; i < D_ / 2; i += 256) tw[i] = g_twD[i];
    for (int d = threadIdx.x; d < D_; d += 256)
        s0[d] = make_float2(tanhf(al * g_x2[row * D_ + d]) * w[d] + bia[d], 0.0f);
    float2* res = block_fft<D_, 256, false>(s0, s1, tw);
    for (int d = threadIdx.x; d < D_; d += 256)
        res[d] = cmul(res[d], make_float2(br[d], bi[d]));
    float2* other = (res == s0) ? s1 : s0;
    float2* r2 = block_fft<D_, 256, true>(res, other, tw);
    const float sc = 1.0f / (float)D_;
    for (int d = threadIdx.x; d < D_; d += 256)
        out[row * D_ + d] = r2[d].x * sc + g_x2[row * D_ + d];
}

// ---------------- launch ----------------
extern "C" void kernel_launch(void* const* d_in, const int* in_sizes, int n_in,
                              void* d_out, int out_size) {
    (void)n_in; (void)out_size;

    const float* x;
    const float *a_qr, *a_qi, *a_kr, *a_ki, *a_vr, *a_vi, *a_rtr, *a_rti;
    const float *b_qr, *b_qi, *b_kr, *b_ki, *b_vr, *b_vi;
    const float *f_br, *f_bi;
    const float *dyta_al, *dyta_w, *dyta_b;
    const float *dytb_al, *dytb_w, *dytb_b;
    const float *dytf_al, *dytf_w, *dytf_b;

    // Disambiguate input ordering via in_sizes: alpha tensors are the only
    // size-1 inputs. Signature order puts dyta_alpha at index 9; setup_inputs
    // dict order puts it at index 20.
    bool sig_order = (in_sizes[9] == 1);

    x = (const float*)d_in[0];
    if (sig_order) {
        a_qr   = (const float*)d_in[1];  a_qi   = (const float*)d_in[2];
        a_kr   = (const float*)d_in[3];  a_ki   = (const float*)d_in[4];
        a_vr   = (const float*)d_in[5];  a_vi   = (const float*)d_in[6];
        a_rtr  = (const float*)d_in[7];  a_rti  = (const float*)d_in[8];
        dyta_al= (const float*)d_in[9];  dyta_w = (const float*)d_in[10]; dyta_b = (const float*)d_in[11];
        b_qr   = (const float*)d_in[12]; b_qi   = (const float*)d_in[13];
        b_kr   = (const float*)d_in[14]; b_ki   = (const float*)d_in[15];
        b_vr   = (const float*)d_in[16]; b_vi   = (const float*)d_in[17];
        dytb_al= (const float*)d_in[18]; dytb_w = (const float*)d_in[19]; dytb_b = (const float*)d_in[20];
        f_br   = (const float*)d_in[23]; f_bi   = (const float*)d_in[24];
        dytf_al= (const float*)d_in[26]; dytf_w = (const float*)d_in[27]; dytf_b = (const float*)d_in[28];
    } else {
        // setup_inputs() dict order:
        // 0:x, 1:a_qr, 2:a_kr, 3:a_vr, 4:a_rtr, 5:b_qr, 6:b_kr, 7:b_vr,
        // 8:f_ar, 9:f_br, 10:a_qi, 11:a_ki, 12:a_vi, 13:a_rti, 14:b_qi,
        // 15:b_ki, 16:b_vi, 17:f_ai, 18:f_bi, 19:f_bias,
        // 20:dyta_alpha, 21:dyta_w, 22:dyta_b,
        // 23:dytb_alpha, 24:dytb_w, 25:dytb_b,
        // 26:dytf_alpha, 27:dytf_w, 28:dytf_b
        a_qr   = (const float*)d_in[1];  a_kr   = (const float*)d_in[2];
        a_vr   = (const float*)d_in[3];  a_rtr  = (const float*)d_in[4];
        b_qr   = (const float*)d_in[5];  b_kr   = (const float*)d_in[6];
        b_vr   = (const float*)d_in[7];
        f_br   = (const float*)d_in[9];
        a_qi   = (const float*)d_in[10]; a_ki   = (const float*)d_in[11];
        a_vi   = (const float*)d_in[12]; a_rti  = (const float*)d_in[13];
        b_qi   = (const float*)d_in[14]; b_ki   = (const float*)d_in[15];
        b_vi   = (const float*)d_in[16];
        f_bi   = (const float*)d_in[18];
        dyta_al= (const float*)d_in[20]; dyta_w = (const float*)d_in[21]; dyta_b = (const float*)d_in[22];
        dytb_al= (const float*)d_in[23]; dytb_w = (const float*)d_in[24]; dytb_b = (const float*)d_in[25];
        dytf_al= (const float*)d_in[26]; dytf_w = (const float*)d_in[27]; dytf_b = (const float*)d_in[28];
    }
    float* out = (float*)d_out;

    kInit<<<4, 256>>>();
    // Block A
    kA1<<<B_ * S_, 256>>>(x, dyta_al, dyta_w, dyta_b);
    kA2<<<B_ * D_, 256>>>(a_qr, a_qi, a_kr, a_ki, a_vr, a_vi, a_rtr, a_rti);
    kA3<<<B_ * S_, 256>>>(x);
    // Block B
    kB1<<<B_ * S_, 256>>>(dytb_al, dytb_w, dytb_b, b_qr, b_qi, b_kr, b_ki, b_vr, b_vi);
    kGemmQK<<<dim3(S_ / BN, S_ / BM, B_), 256>>>();
    kSoftmax<<<B_ * S_, 256>>>();
    kGemmPV<<<dim3(D_ / BN, S_ / BM, B_), 256>>>();
    // Block C
    kC<<<B_ * S_, 256>>>(dytf_al, dytf_w, dytf_b, f_br, f_bi, out);
}

// round 15
// speedup vs baseline: 1.6472x; 1.6472x over previous
#include <cuda_runtime.h>
#include <cuda_bf16.h>
#include <math.h>
#include <stdint.h>

// Problem dims
constexpr int B_ = 4;
constexpr int S_ = 2048;
constexpr int D_ = 512;
constexpr size_t NTOT = (size_t)B_ * S_ * D_;

constexpr int KQK = 3 * D_;     // 1536  (hi*hi + hi*lo + lo*hi)
constexpr int KPV = 3 * S_;     // 6144

// ---------------- scratch (static __device__, no allocation) ----------------
__device__ float2 g_c1[NTOT];                       // 32 MB complex work (block A)
__device__ float  g_x1[NTOT];                       // x after block A
__device__ float  g_x2[NTOT];                       // x after block B
__device__ float  g_v [NTOT];                       // v fp32 (pre-transpose)
__device__ float  g_sc[(size_t)B_ * S_ * S_];       // 64 MB scores (fp32)
__device__ __nv_bfloat16 g_qcat[(size_t)B_ * S_ * KQK];   // 25 MB
__device__ __nv_bfloat16 g_kcat[(size_t)B_ * S_ * KQK];   // 25 MB
__device__ __nv_bfloat16 g_vt  [(size_t)B_ * D_ * KPV];   // 25 MB (V^T, split)
__device__ __nv_bfloat16 g_pcat[(size_t)B_ * S_ * KPV];   // 100 MB
__device__ float2 g_twS[S_ / 2];                    // twiddles W_2048^k
__device__ float2 g_twD[D_ / 2];                    // twiddles W_512^k

// ---------------- helpers ----------------
__device__ __forceinline__ uint32_t smem_u32(const void* p) {
    uint32_t a;
    asm("{ .reg .u64 t; cvta.to.shared.u64 t, %1; cvt.u32.u64 %0, t; }" : "=r"(a) : "l"(p));
    return a;
}
__device__ __forceinline__ uint32_t sw128(uint32_t off) { return off ^ ((off >> 3) & 0x70); }

__device__ __forceinline__ float2 cmul(float2 a, float2 b) {
    return make_float2(a.x * b.x - a.y * b.y, a.x * b.y + a.y * b.x);
}

// Stockham auto-sort radix-2 FFT in shared memory.
template <int N, int NT, bool INV>
__device__ __forceinline__ float2* block_fft(float2* s0, float2* s1, const float2* tw) {
    float2* src = s0;
    float2* dst = s1;
    int n = N, s = 1;
    while (n > 1) {
        __syncthreads();
        #pragma unroll 4
        for (int idx = threadIdx.x; idx < N / 2; idx += NT) {
            int base = idx & ~(s - 1);
            float2 w = tw[base];
            if (INV) w.y = -w.y;
            float2 a = src[idx];
            float2 b = src[idx + N / 2];
            float2 u = make_float2(a.x - b.x, a.y - b.y);
            dst[idx + base]     = make_float2(a.x + b.x, a.y + b.y);
            dst[idx + base + s] = make_float2(u.x * w.x - u.y * w.y,
                                              u.x * w.y + u.y * w.x);
        }
        float2* t = src; src = dst; dst = t;
        n >>= 1; s <<= 1;
    }
    __syncthreads();
    return src;
}

// ---------------- init: twiddles ----------------
__global__ void kInit() {
    int i = blockIdx.x * blockDim.x + threadIdx.x;
    if (i < S_ / 2) {
        float sn, cs;
        sincosf(-6.283185307179586476f * (float)i / (float)S_, &sn, &cs);
        g_twS[i] = make_float2(cs, sn);
    }
    if (i < D_ / 2) {
        float sn, cs;
        sincosf(-6.283185307179586476f * (float)i / (float)D_, &sn, &cs);
        g_twD[i] = make_float2(cs, sn);
    }
}

// ---------------- Block A ----------------
__global__ void __launch_bounds__(256) kA1(const float* __restrict__ x,
                                           const float* __restrict__ alpha,
                                           const float* __restrict__ w,
                                           const float* __restrict__ bia) {
    __shared__ float2 s0[D_], s1[D_], tw[D_ / 2];
    size_t row = blockIdx.x;
    float al = alpha[0];
    for (int i = threadIdx.x; i < D_ / 2; i += 256) tw[i] = g_twD[i];
    const float* xr = x + row * D_;
    for (int d = threadIdx.x; d < D_; d += 256) {
        float v = tanhf(al * xr[d]) * w[d] + bia[d];
        s0[d] = make_float2(v, 0.0f);
    }
    float2* res = block_fft<D_, 256, false>(s0, s1, tw);
    for (int d = threadIdx.x; d < D_; d += 256) g_c1[row * D_ + d] = res[d];
}

__global__ void __launch_bounds__(256) kA2(const float* __restrict__ qr, const float* __restrict__ qi,
                                           const float* __restrict__ kr, const float* __restrict__ ki,
                                           const float* __restrict__ vr, const float* __restrict__ vi,
                                           const float* __restrict__ rtr, const float* __restrict__ rti) {
    __shared__ float2 s0[S_], s1[S_], tw[S_ / 2];
    int b = blockIdx.x / D_;
    int d = blockIdx.x % D_;
    for (int i = threadIdx.x; i < S_ / 2; i += 256) tw[i] = g_twS[i];
    float2 qw = make_float2(qr[d], qi[d]);
    float2 kw = make_float2(kr[d], ki[d]);
    float2 vw = make_float2(vr[d], vi[d]);
    float2 rw = make_float2(rtr[d], rti[d]);
    float2* col = g_c1 + (size_t)b * S_ * D_ + d;
    for (int s = threadIdx.x; s < S_; s += 256) s0[s] = col[(size_t)s * D_];
    float2* F = block_fft<S_, 256, false>(s0, s1, tw);
    for (int i = threadIdx.x; i < S_; i += 256) {
        float2 f = F[i];
        float2 q = cmul(qw, f);
        float2 k = cmul(kw, f);
        float2 v = cmul(vw, f);
        k.x += 1e-12f;
        float inv = 1.0f / (k.x * k.x + k.y * k.y);
        float2 u = make_float2((q.x * k.x + q.y * k.y) * inv,
                               (q.y * k.x - q.x * k.y) * inv);
        F[i] = cmul(u, v);
    }
    float2* other = (F == s0) ? s1 : s0;
    float2* res = block_fft<S_, 256, true>(F, other, tw);
    const float sc = 1.0f / (float)S_;
    for (int i = threadIdx.x; i < S_; i += 256) {
        float2 r = cmul(res[i], rw);
        col[(size_t)i * D_] = make_float2(r.x * sc, r.y * sc);
    }
}

__global__ void __launch_bounds__(256) kA3(const float* __restrict__ x) {
    __shared__ float2 s0[D_], s1[D_], tw[D_ / 2];
    size_t row = blockIdx.x;
    for (int i = threadIdx.x; i < D_ / 2; i += 256) tw[i] = g_twD[i];
    for (int d = threadIdx.x; d < D_; d += 256) s0[d] = g_c1[row * D_ + d];
    float2* res = block_fft<D_, 256, true>(s0, s1, tw);
    const float sc = 1.0f / (float)D_;
    for (int d = threadIdx.x; d < D_; d += 256)
        g_x1[row * D_ + d] = res[d].x * sc + x[row * D_ + d];
}

// ---------------- Block B: projections (writes split-bf16 operands) ----------------
__global__ void __launch_bounds__(256) kB1(const float* __restrict__ alpha,
                                           const float* __restrict__ w,
                                           const float* __restrict__ bia,
                                           const float* __restrict__ qr, const float* __restrict__ qi,
                                           const float* __restrict__ kr, const float* __restrict__ ki,
                                           const float* __restrict__ vr, const float* __restrict__ vi) {
    __shared__ float2 s0[D_], s1[D_], sXf[D_], tw[D_ / 2];
    size_t row = blockIdx.x;
    float al = alpha[0];
    for (int i = threadIdx.x; i < D_ / 2; i += 256) tw[i] = g_twD[i];
    for (int d = threadIdx.x; d < D_; d += 256)
        s0[d] = make_float2(tanhf(al * g_x1[row * D_ + d]) * w[d] + bia[d], 0.0f);
    float2* res = block_fft<D_, 256, false>(s0, s1, tw);
    for (int d = threadIdx.x; d < D_; d += 256) sXf[d] = res[d];
    __syncthreads();
    const float sc = 1.0f / (float)D_;
    const float qsc = sc * 0.044194173824159216f;   // fold 1/sqrt(512) into q
    __nv_bfloat16* qc = g_qcat + row * KQK;
    __nv_bfloat16* kc = g_kcat + row * KQK;
    // q: slots [hi, hi, lo]
    for (int d = threadIdx.x; d < D_; d += 256)
        s0[d] = cmul(sXf[d], make_float2(qr[d], qi[d]));
    res = block_fft<D_, 256, true>(s0, s1, tw);
    for (int d = threadIdx.x; d < D_; d += 256) {
        float v = res[d].x * qsc;
        __nv_bfloat16 h = __float2bfloat16(v);
        __nv_bfloat16 l = __float2bfloat16(v - __bfloat162float(h));
        qc[d] = h; qc[D_ + d] = h; qc[2 * D_ + d] = l;
    }
    __syncthreads();
    // k: slots [hi, lo, hi]
    for (int d = threadIdx.x; d < D_; d += 256)
        s0[d] = cmul(sXf[d], make_float2(kr[d], ki[d]));
    res = block_fft<D_, 256, true>(s0, s1, tw);
    for (int d = threadIdx.x; d < D_; d += 256) {
        float v = res[d].x * sc;
        __nv_bfloat16 h = __float2bfloat16(v);
        __nv_bfloat16 l = __float2bfloat16(v - __bfloat162float(h));
        kc[d] = h; kc[D_ + d] = l; kc[2 * D_ + d] = h;
    }
    __syncthreads();
    // v: fp32 (transposed+split later)
    for (int d = threadIdx.x; d < D_; d += 256)
        s0[d] = cmul(sXf[d], make_float2(vr[d], vi[d]));
    res = block_fft<D_, 256, true>(s0, s1, tw);
    for (int d = threadIdx.x; d < D_; d += 256) g_v[row * D_ + d] = res[d].x * sc;
}

// V transpose + split: vt[b][n][t]=hi(v), [n][S+t]=lo(v), [n][2S+t]=hi(v)
__global__ void __launch_bounds__(256) kVT() {
    __shared__ float tile[32][33];
    int b = blockIdx.z;
    int n0 = blockIdx.x * 32;
    int t0 = blockIdx.y * 32;
    int tx = threadIdx.x & 31, ty = threadIdx.x >> 5;   // 32 x 8
    const float* V = g_v + (size_t)b * S_ * D_;
    #pragma unroll
    for (int j = 0; j < 4; j++)
        tile[ty + j * 8][tx] = V[(size_t)(t0 + ty + j * 8) * D_ + n0 + tx];
    __syncthreads();
    __nv_bfloat16* VT = g_vt + (size_t)b * D_ * KPV;
    #pragma unroll
    for (int j = 0; j < 4; j++) {
        int n = n0 + ty + j * 8;
        float v = tile[tx][ty + j * 8];
        __nv_bfloat16 h = __float2bfloat16(v);
        __nv_bfloat16 l = __float2bfloat16(v - __bfloat162float(h));
        size_t base = (size_t)n * KPV + t0 + tx;
        VT[base] = h; VT[base + S_] = l; VT[base + 2 * S_] = h;
    }
}

// ---------------- mma.sync bf16 GEMM: 128x128 CTA tile, BK=64, double-buffered ----------------
// A: [Mb, KTOT] row-major bf16, B: [Nb, KTOT] row-major bf16 (i.e. B^T col-major),
// C[m,n] = sum_k A[m,k] B[n,k]  (fp32 accum), optional residual add.
template <int KTOT, bool RESID>
__global__ void __launch_bounds__(256, 1) kMMA(const __nv_bfloat16* __restrict__ Ag,
                                               const __nv_bfloat16* __restrict__ Bg,
                                               float* __restrict__ Cg,
                                               const float* __restrict__ Rg,
                                               int Mb, int Nb, int ldc) {
    extern __shared__ char smem[];
    constexpr int NCH = KTOT / 64;
    const int tid = threadIdx.x, wid = tid >> 5, lane = tid & 31;
    const int wm = wid & 3, wn = wid >> 2;           // warp grid 4 (m) x 2 (n)
    const int b = blockIdx.z, m0 = blockIdx.y * 128, n0 = blockIdx.x * 128;
    const __nv_bfloat16* Arow = Ag + ((size_t)b * Mb + m0) * KTOT;
    const __nv_bfloat16* Brow = Bg + ((size_t)b * Nb + n0) * KTOT;

    float acc[2][8][4] = {};                          // [mi][nf][reg]

    // chunk load via cp.async: 128 rows x 64 bf16 (=128B) per operand
    auto load_chunk = [&](int c, int buf) {
        int k0 = c * 64;
        char* sA = smem + buf * 32768;
        char* sB = smem + buf * 32768 + 16384;
        #pragma unroll
        for (int i = 0; i < 4; i++) {
            int idx = i * 256 + tid;                  // 0..1023
            int r = idx >> 3, cc = idx & 7;
            uint32_t off = sw128((uint32_t)(r * 128 + cc * 16));
            uint32_t dA = smem_u32(sA + off);
            const __nv_bfloat16* srcA = Arow + (size_t)r * KTOT + k0 + cc * 8;
            asm volatile("cp.async.cg.shared.global [%0], [%1], 16;" :: "r"(dA), "l"(srcA));
            uint32_t dB = smem_u32(sB + off);
            const __nv_bfloat16* srcB = Brow + (size_t)r * KTOT + k0 + cc * 8;
            asm volatile("cp.async.cg.shared.global [%0], [%1], 16;" :: "r"(dB), "l"(srcB));
        }
        asm volatile("cp.async.commit_group;" ::: "memory");
    };

    load_chunk(0, 0);
    for (int c = 0; c < NCH; c++) {
        int buf = c & 1;
        if (c + 1 < NCH) {
            load_chunk(c + 1, buf ^ 1);
            asm volatile("cp.async.wait_group 1;" ::: "memory");
        } else {
            asm volatile("cp.async.wait_group 0;" ::: "memory");
        }
        __syncthreads();
        const char* sA = smem + buf * 32768;
        const char* sB = smem + buf * 32768 + 16384;
        #pragma unroll
        for (int ks = 0; ks < 4; ks++) {
            const int kk = ks * 16;
            uint32_t af[2][4], bf[4][4];
            #pragma unroll
            for (int mi = 0; mi < 2; mi++) {
                int row = wm * 32 + mi * 16 + (lane & 15);
                int col = kk + ((lane >> 4) << 3);
                uint32_t addr = smem_u32(sA + sw128((uint32_t)(row * 128 + col * 2)));
                asm volatile("ldmatrix.sync.aligned.m8n8.x4.shared.b16 {%0,%1,%2,%3}, [%4];"
                    : "=r"(af[mi][0]), "=r"(af[mi][1]), "=r"(af[mi][2]), "=r"(af[mi][3])
                    : "r"(addr));
            }
            #pragma unroll
            for (int nj = 0; nj < 4; nj++) {
                // matrices: [n0-7,k0-7], [n0-7,k8-15], [n8-15,k0-7], [n8-15,k8-15]
                int nr = wn * 64 + nj * 16 + ((lane >> 4) << 3) + (lane & 7);
                int kc = kk + (((lane >> 3) & 1) << 3);
                uint32_t addr = smem_u32(sB + sw128((uint32_t)(nr * 128 + kc * 2)));
                asm volatile("ldmatrix.sync.aligned.m8n8.x4.shared.b16 {%0,%1,%2,%3}, [%4];"
                    : "=r"(bf[nj][0]), "=r"(bf[nj][1]), "=r"(bf[nj][2]), "=r"(bf[nj][3])
                    : "r"(addr));
            }
            #pragma unroll
            for (int mi = 0; mi < 2; mi++) {
                #pragma unroll
                for (int nj = 0; nj < 4; nj++) {
                    float* c0 = acc[mi][nj * 2];
                    asm volatile(
                        "mma.sync.aligned.m16n8k16.row.col.f32.bf16.bf16.f32 "
                        "{%0,%1,%2,%3}, {%4,%5,%6,%7}, {%8,%9}, {%0,%1,%2,%3};"
                        : "+f"(c0[0]), "+f"(c0[1]), "+f"(c0[2]), "+f"(c0[3])
                        : "r"(af[mi][0]), "r"(af[mi][1]), "r"(af[mi][2]), "r"(af[mi][3]),
                          "r"(bf[nj][0]), "r"(bf[nj][1]));
                    float* c1 = acc[mi][nj * 2 + 1];
                    asm volatile(
                        "mma.sync.aligned.m16n8k16.row.col.f32.bf16.bf16.f32 "
                        "{%0,%1,%2,%3}, {%4,%5,%6,%7}, {%8,%9}, {%0,%1,%2,%3};"
                        : "+f"(c1[0]), "+f"(c1[1]), "+f"(c1[2]), "+f"(c1[3])
                        : "r"(af[mi][0]), "r"(af[mi][1]), "r"(af[mi][2]), "r"(af[mi][3]),
                          "r"(bf[nj][2]), "r"(bf[nj][3]));
                }
            }
        }
        __syncthreads();
    }

    // Epilogue: C frag m16n8 -> thread holds (row lane/4, cols (lane%4)*2..+1) and (+8 row)
    #pragma unroll
    for (int mi = 0; mi < 2; mi++) {
        int row = m0 + wm * 32 + mi * 16 + (lane >> 2);
        size_t base = ((size_t)b * Mb + row) * ldc + n0 + wn * 64 + (lane & 3) * 2;
        #pragma unroll
        for (int nf = 0; nf < 8; nf++) {
            size_t o = base + nf * 8;
            float2 v0 = make_float2(acc[mi][nf][0], acc[mi][nf][1]);
            float2 v1 = make_float2(acc[mi][nf][2], acc[mi][nf][3]);
            if (RESID) {
                float2 r0 = *(const float2*)(Rg + o);
                float2 r1 = *(const float2*)(Rg + o + 8 * (size_t)ldc);
                v0.x += r0.x; v0.y += r0.y;
                v1.x += r1.x; v1.y += r1.y;
            }
            *(float2*)(Cg + o) = v0;
            *(float2*)(Cg + o + 8 * (size_t)ldc) = v1;
        }
    }
}

// softmax over rows of g_sc, writes split-bf16 Pcat: [hi, hi, lo]
__global__ void __launch_bounds__(256) kSoftmax() {
    __shared__ float red[256];
    size_t row = blockIdx.x;
    const float* r = g_sc + row * S_;
    __nv_bfloat16* pc = g_pcat + row * KPV;
    float vals[8];
    float mx = -1e30f;
    #pragma unroll
    for (int i = 0; i < 8; i++) {
        vals[i] = r[threadIdx.x + i * 256];
        mx = fmaxf(mx, vals[i]);
    }
    red[threadIdx.x] = mx;
    __syncthreads();
    for (int off = 128; off > 0; off >>= 1) {
        if (threadIdx.x < off)
            red[threadIdx.x] = fmaxf(red[threadIdx.x], red[threadIdx.x + off]);
        __syncthreads();
    }
    mx = red[0];
    __syncthreads();
    float sum = 0.0f;
    #pragma unroll
    for (int i = 0; i < 8; i++) {
        vals[i] = __expf(vals[i] - mx);
        sum += vals[i];
    }
    red[threadIdx.x] = sum;
    __syncthreads();
    for (int off = 128; off > 0; off >>= 1) {
        if (threadIdx.x < off) red[threadIdx.x] += red[threadIdx.x + off];
        __syncthreads();
    }
    float inv = 1.0f / red[0];
    #pragma unroll
    for (int i = 0; i < 8; i++) {
        int t = threadIdx.x + i * 256;
        float p = vals[i] * inv;
        __nv_bfloat16 h = __float2bfloat16(p);
        __nv_bfloat16 l = __float2bfloat16(p - __bfloat162float(h));
        pc[t] = h; pc[S_ + t] = h; pc[2 * S_ + t] = l;
    }
}

// ---------------- Block C: FFN ----------------
__global__ void __launch_bounds__(256) kC(const float* __restrict__ alpha,
                                          const float* __restrict__ w,
                                          const float* __restrict__ bia,
                                          const float* __restrict__ br,
                                          const float* __restrict__ bi,
                                          float* __restrict__ out) {
    __shared__ float2 s0[D_], s1[D_], tw[D_ / 2];
    size_t row = blockIdx.x;
    float al = alpha[0];
    for (int i = threadIdx.x; i < D_ / 2; i += 256) tw[i] = g_twD[i];
    for (int d = threadIdx.x; d < D_; d += 256)
        s0[d] = make_float2(tanhf(al * g_x2[row * D_ + d]) * w[d] + bia[d], 0.0f);
    float2* res = block_fft<D_, 256, false>(s0, s1, tw);
    for (int d = threadIdx.x; d < D_; d += 256)
        res[d] = cmul(res[d], make_float2(br[d], bi[d]));
    float2* other = (res == s0) ? s1 : s0;
    float2* r2 = block_fft<D_, 256, true>(res, other, tw);
    const float sc = 1.0f / (float)D_;
    for (int d = threadIdx.x; d < D_; d += 256)
        out[row * D_ + d] = r2[d].x * sc + g_x2[row * D_ + d];
}

// ---------------- launch ----------------
extern "C" void kernel_launch(void* const* d_in, const int* in_sizes, int n_in,
                              void* d_out, int out_size) {
    (void)n_in; (void)out_size;

    const float* x;
    const float *a_qr, *a_qi, *a_kr, *a_ki, *a_vr, *a_vi, *a_rtr, *a_rti;
    const float *b_qr, *b_qi, *b_kr, *b_ki, *b_vr, *b_vi;
    const float *f_br, *f_bi;
    const float *dyta_al, *dyta_w, *dyta_b;
    const float *dytb_al, *dytb_w, *dytb_b;
    const float *dytf_al, *dytf_w, *dytf_b;

    bool sig_order = (in_sizes[9] == 1);
    x = (const float*)d_in[0];
    if (sig_order) {
        a_qr   = (const float*)d_in[1];  a_qi   = (const float*)d_in[2];
        a_kr   = (const float*)d_in[3];  a_ki   = (const float*)d_in[4];
        a_vr   = (const float*)d_in[5];  a_vi   = (const float*)d_in[6];
        a_rtr  = (const float*)d_in[7];  a_rti  = (const float*)d_in[8];
        dyta_al= (const float*)d_in[9];  dyta_w = (const float*)d_in[10]; dyta_b = (const float*)d_in[11];
        b_qr   = (const float*)d_in[12]; b_qi   = (const float*)d_in[13];
        b_kr   = (const float*)d_in[14]; b_ki   = (const float*)d_in[15];
        b_vr   = (const float*)d_in[16]; b_vi   = (const float*)d_in[17];
        dytb_al= (const float*)d_in[18]; dytb_w = (const float*)d_in[19]; dytb_b = (const float*)d_in[20];
        f_br   = (const float*)d_in[23]; f_bi   = (const float*)d_in[24];
        dytf_al= (const float*)d_in[26]; dytf_w = (const float*)d_in[27]; dytf_b = (const float*)d_in[28];
    } else {
        a_qr   = (const float*)d_in[1];  a_kr   = (const float*)d_in[2];
        a_vr   = (const float*)d_in[3];  a_rtr  = (const float*)d_in[4];
        b_qr   = (const float*)d_in[5];  b_kr   = (const float*)d_in[6];
        b_vr   = (const float*)d_in[7];
        f_br   = (const float*)d_in[9];
        a_qi   = (const float*)d_in[10]; a_ki   = (const float*)d_in[11];
        a_vi   = (const float*)d_in[12]; a_rti  = (const float*)d_in[13];
        b_qi   = (const float*)d_in[14]; b_ki   = (const float*)d_in[15];
        b_vi   = (const float*)d_in[16];
        f_bi   = (const float*)d_in[18];
        dyta_al= (const float*)d_in[20]; dyta_w = (const float*)d_in[21]; dyta_b = (const float*)d_in[22];
        dytb_al= (const float*)d_in[23]; dytb_w = (const float*)d_in[24]; dytb_b = (const float*)d_in[25];
        dytf_al= (const float*)d_in[26]; dytf_w = (const float*)d_in[27]; dytf_b = (const float*)d_in[28];
    }
    float* out = (float*)d_out;

    constexpr int GEMM_SMEM = 2 * 32768;   // 64 KB (double-buffered A+B)
    cudaFuncSetAttribute(kMMA<KQK, false>, cudaFuncAttributeMaxDynamicSharedMemorySize, GEMM_SMEM);
    cudaFuncSetAttribute(kMMA<KPV, true>,  cudaFuncAttributeMaxDynamicSharedMemorySize, GEMM_SMEM);

    float* g_sc_p;   cudaGetSymbolAddress((void**)&g_sc_p, g_sc);
    float* g_x1_p;   cudaGetSymbolAddress((void**)&g_x1_p, g_x1);
    float* g_x2_p;   cudaGetSymbolAddress((void**)&g_x2_p, g_x2);
    __nv_bfloat16 *qc_p, *kc_p, *vt_p, *pc_p;
    cudaGetSymbolAddress((void**)&qc_p, g_qcat);
    cudaGetSymbolAddress((void**)&kc_p, g_kcat);
    cudaGetSymbolAddress((void**)&vt_p, g_vt);
    cudaGetSymbolAddress((void**)&pc_p, g_pcat);

    kInit<<<4, 256>>>();
    // Block A
    kA1<<<B_ * S_, 256>>>(x, dyta_al, dyta_w, dyta_b);
    kA2<<<B_ * D_, 256>>>(a_qr, a_qi, a_kr, a_ki, a_vr, a_vi, a_rtr, a_rti);
    kA3<<<B_ * S_, 256>>>(x);
    // Block B
    kB1<<<B_ * S_, 256>>>(dytb_al, dytb_w, dytb_b, b_qr, b_qi, b_kr, b_ki, b_vr, b_vi);
    kVT<<<dim3(D_ / 32, S_ / 32, B_), 256>>>();
    // QK^T -> scores (scale folded into qcat)
    kMMA<KQK, false><<<dim3(S_ / 128, S_ / 128, B_), 256, GEMM_SMEM>>>(
        qc_p, kc_p, g_sc_p, nullptr, S_, S_, S_);
    kSoftmax<<<B_ * S_, 256>>>();
    // P·V + x1 -> x2
    kMMA<KPV, true><<<dim3(D_ / 128, S_ / 128, B_), 256, GEMM_SMEM>>>(
        pc_p, vt_p, g_x2_p, g_x1_p, S_, D_, D_);
    // Block C
    kC<<<B_ * S_, 256>>>(dytf_al, dytf_w, dytf_b, f_br, f_bi, out);
}

// round 16
// speedup vs baseline: 1.6478x; 1.0004x over previous
#include <cuda_runtime.h>
#include <cuda_bf16.h>
#include <math.h>
#include <stdint.h>

// Problem dims
constexpr int B_ = 4;
constexpr int S_ = 2048;
constexpr int D_ = 512;
constexpr size_t NTOT = (size_t)B_ * S_ * D_;

constexpr int KQK = 3 * D_;     // 1536  (hi*hi + hi*lo + lo*hi)
constexpr int KPV = 3 * S_;     // 6144

// ---------------- scratch (static __device__, no allocation) ----------------
__device__ float2 g_c1[NTOT];                       // 32 MB complex work (block A)
__device__ float  g_x1[NTOT];                       // x after block A
__device__ float  g_x2[NTOT];                       // x after block B
__device__ float  g_v [NTOT];                       // v fp32 (pre-transpose)
__device__ float  g_sc[(size_t)B_ * S_ * S_];       // 64 MB scores (fp32)
__device__ __nv_bfloat16 g_qcat[(size_t)B_ * S_ * KQK];   // 25 MB
__device__ __nv_bfloat16 g_kcat[(size_t)B_ * S_ * KQK];   // 25 MB
__device__ __nv_bfloat16 g_vt  [(size_t)B_ * D_ * KPV];   // 25 MB (V^T, split)
__device__ __nv_bfloat16 g_pcat[(size_t)B_ * S_ * KPV];   // 100 MB
__device__ float2 g_twS[S_ / 2];                    // twiddles W_2048^k
__device__ float2 g_twD[D_ / 2];                    // twiddles W_512^k

// ---------------- helpers ----------------
__device__ __forceinline__ uint32_t smem_u32(const void* p) {
    uint32_t a;
    asm("{ .reg .u64 t; cvta.to.shared.u64 t, %1; cvt.u32.u64 %0, t; }" : "=r"(a) : "l"(p));
    return a;
}
__device__ __forceinline__ uint32_t sw128(uint32_t off) { return off ^ ((off >> 3) & 0x70); }

__device__ __forceinline__ float2 cmul(float2 a, float2 b) {
    return make_float2(a.x * b.x - a.y * b.y, a.x * b.y + a.y * b.x);
}

// Stockham auto-sort radix-2 FFT in shared memory.
template <int N, int NT, bool INV>
__device__ __forceinline__ float2* block_fft(float2* s0, float2* s1, const float2* tw) {
    float2* src = s0;
    float2* dst = s1;
    int n = N, s = 1;
    while (n > 1) {
        __syncthreads();
        #pragma unroll 4
        for (int idx = threadIdx.x; idx < N / 2; idx += NT) {
            int base = idx & ~(s - 1);
            float2 w = tw[base];
            if (INV) w.y = -w.y;
            float2 a = src[idx];
            float2 b = src[idx + N / 2];
            float2 u = make_float2(a.x - b.x, a.y - b.y);
            dst[idx + base]     = make_float2(a.x + b.x, a.y + b.y);
            dst[idx + base + s] = make_float2(u.x * w.x - u.y * w.y,
                                              u.x * w.y + u.y * w.x);
        }
        float2* t = src; src = dst; dst = t;
        n >>= 1; s <<= 1;
    }
    __syncthreads();
    return src;
}

// ---------------- init: twiddles ----------------
__global__ void kInit() {
    int i = blockIdx.x * blockDim.x + threadIdx.x;
    if (i < S_ / 2) {
        float sn, cs;
        sincosf(-6.283185307179586476f * (float)i / (float)S_, &sn, &cs);
        g_twS[i] = make_float2(cs, sn);
    }
    if (i < D_ / 2) {
        float sn, cs;
        sincosf(-6.283185307179586476f * (float)i / (float)D_, &sn, &cs);
        g_twD[i] = make_float2(cs, sn);
    }
}

// ---------------- Block A ----------------
__global__ void __launch_bounds__(256) kA1(const float* __restrict__ x,
                                           const float* __restrict__ alpha,
                                           const float* __restrict__ w,
                                           const float* __restrict__ bia) {
    __shared__ float2 s0[D_], s1[D_], tw[D_ / 2];
    size_t row = blockIdx.x;
    float al = alpha[0];
    for (int i = threadIdx.x; i < D_ / 2; i += 256) tw[i] = g_twD[i];
    const float* xr = x + row * D_;
    for (int d = threadIdx.x; d < D_; d += 256) {
        float v = tanhf(al * xr[d]) * w[d] + bia[d];
        s0[d] = make_float2(v, 0.0f);
    }
    float2* res = block_fft<D_, 256, false>(s0, s1, tw);
    for (int d = threadIdx.x; d < D_; d += 256) g_c1[row * D_ + d] = res[d];
}

__global__ void __launch_bounds__(256) kA2(const float* __restrict__ qr, const float* __restrict__ qi,
                                           const float* __restrict__ kr, const float* __restrict__ ki,
                                           const float* __restrict__ vr, const float* __restrict__ vi,
                                           const float* __restrict__ rtr, const float* __restrict__ rti) {
    __shared__ float2 s0[S_], s1[S_], tw[S_ / 2];
    int b = blockIdx.x / D_;
    int d = blockIdx.x % D_;
    for (int i = threadIdx.x; i < S_ / 2; i += 256) tw[i] = g_twS[i];
    float2 qw = make_float2(qr[d], qi[d]);
    float2 kw = make_float2(kr[d], ki[d]);
    float2 vw = make_float2(vr[d], vi[d]);
    float2 rw = make_float2(rtr[d], rti[d]);
    float2* col = g_c1 + (size_t)b * S_ * D_ + d;
    for (int s = threadIdx.x; s < S_; s += 256) s0[s] = col[(size_t)s * D_];
    float2* F = block_fft<S_, 256, false>(s0, s1, tw);
    for (int i = threadIdx.x; i < S_; i += 256) {
        float2 f = F[i];
        float2 q = cmul(qw, f);
        float2 k = cmul(kw, f);
        float2 v = cmul(vw, f);
        k.x += 1e-12f;
        float inv = 1.0f / (k.x * k.x + k.y * k.y);
        float2 u = make_float2((q.x * k.x + q.y * k.y) * inv,
                               (q.y * k.x - q.x * k.y) * inv);
        F[i] = cmul(u, v);
    }
    float2* other = (F == s0) ? s1 : s0;
    float2* res = block_fft<S_, 256, true>(F, other, tw);
    const float sc = 1.0f / (float)S_;
    for (int i = threadIdx.x; i < S_; i += 256) {
        float2 r = cmul(res[i], rw);
        col[(size_t)i * D_] = make_float2(r.x * sc, r.y * sc);
    }
}

__global__ void __launch_bounds__(256) kA3(const float* __restrict__ x) {
    __shared__ float2 s0[D_], s1[D_], tw[D_ / 2];
    size_t row = blockIdx.x;
    for (int i = threadIdx.x; i < D_ / 2; i += 256) tw[i] = g_twD[i];
    for (int d = threadIdx.x; d < D_; d += 256) s0[d] = g_c1[row * D_ + d];
    float2* res = block_fft<D_, 256, true>(s0, s1, tw);
    const float sc = 1.0f / (float)D_;
    for (int d = threadIdx.x; d < D_; d += 256)
        g_x1[row * D_ + d] = res[d].x * sc + x[row * D_ + d];
}

// ---------------- Block B: projections (writes split-bf16 operands) ----------------
__global__ void __launch_bounds__(256) kB1(const float* __restrict__ alpha,
                                           const float* __restrict__ w,
                                           const float* __restrict__ bia,
                                           const float* __restrict__ qr, const float* __restrict__ qi,
                                           const float* __restrict__ kr, const float* __restrict__ ki,
                                           const float* __restrict__ vr, const float* __restrict__ vi) {
    __shared__ float2 s0[D_], s1[D_], sXf[D_], tw[D_ / 2];
    size_t row = blockIdx.x;
    float al = alpha[0];
    for (int i = threadIdx.x; i < D_ / 2; i += 256) tw[i] = g_twD[i];
    for (int d = threadIdx.x; d < D_; d += 256)
        s0[d] = make_float2(tanhf(al * g_x1[row * D_ + d]) * w[d] + bia[d], 0.0f);
    float2* res = block_fft<D_, 256, false>(s0, s1, tw);
    for (int d = threadIdx.x; d < D_; d += 256) sXf[d] = res[d];
    __syncthreads();
    const float sc = 1.0f / (float)D_;
    const float qsc = sc * 0.044194173824159216f;   // fold 1/sqrt(512) into q
    __nv_bfloat16* qc = g_qcat + row * KQK;
    __nv_bfloat16* kc = g_kcat + row * KQK;
    // q: slots [hi, hi, lo]
    for (int d = threadIdx.x; d < D_; d += 256)
        s0[d] = cmul(sXf[d], make_float2(qr[d], qi[d]));
    res = block_fft<D_, 256, true>(s0, s1, tw);
    for (int d = threadIdx.x; d < D_; d += 256) {
        float v = res[d].x * qsc;
        __nv_bfloat16 h = __float2bfloat16(v);
        __nv_bfloat16 l = __float2bfloat16(v - __bfloat162float(h));
        qc[d] = h; qc[D_ + d] = h; qc[2 * D_ + d] = l;
    }
    __syncthreads();
    // k: slots [hi, lo, hi]
    for (int d = threadIdx.x; d < D_; d += 256)
        s0[d] = cmul(sXf[d], make_float2(kr[d], ki[d]));
    res = block_fft<D_, 256, true>(s0, s1, tw);
    for (int d = threadIdx.x; d < D_; d += 256) {
        float v = res[d].x * sc;
        __nv_bfloat16 h = __float2bfloat16(v);
        __nv_bfloat16 l = __float2bfloat16(v - __bfloat162float(h));
        kc[d] = h; kc[D_ + d] = l; kc[2 * D_ + d] = h;
    }
    __syncthreads();
    // v: fp32 (transposed+split later)
    for (int d = threadIdx.x; d < D_; d += 256)
        s0[d] = cmul(sXf[d], make_float2(vr[d], vi[d]));
    res = block_fft<D_, 256, true>(s0, s1, tw);
    for (int d = threadIdx.x; d < D_; d += 256) g_v[row * D_ + d] = res[d].x * sc;
}

// V transpose + split: vt[b][n][t]=hi(v), [n][S+t]=lo(v), [n][2S+t]=hi(v)
__global__ void __launch_bounds__(256) kVT() {
    __shared__ float tile[32][33];
    int b = blockIdx.z;
    int n0 = blockIdx.x * 32;
    int t0 = blockIdx.y * 32;
    int tx = threadIdx.x & 31, ty = threadIdx.x >> 5;   // 32 x 8
    const float* V = g_v + (size_t)b * S_ * D_;
    #pragma unroll
    for (int j = 0; j < 4; j++)
        tile[ty + j * 8][tx] = V[(size_t)(t0 + ty + j * 8) * D_ + n0 + tx];
    __syncthreads();
    __nv_bfloat16* VT = g_vt + (size_t)b * D_ * KPV;
    #pragma unroll
    for (int j = 0; j < 4; j++) {
        int n = n0 + ty + j * 8;
        float v = tile[tx][ty + j * 8];
        __nv_bfloat16 h = __float2bfloat16(v);
        __nv_bfloat16 l = __float2bfloat16(v - __bfloat162float(h));
        size_t base = (size_t)n * KPV + t0 + tx;
        VT[base] = h; VT[base + S_] = l; VT[base + 2 * S_] = h;
    }
}

// ---------------- mma.sync bf16 GEMM: 128x128 CTA tile, BK=64, double-buffered ----------------
// A: [Mb, KTOT] row-major bf16, B: [Nb, KTOT] row-major bf16 (i.e. B^T col-major),
// C[m,n] = sum_k A[m,k] B[n,k]  (fp32 accum), optional residual add.
template <int KTOT, bool RESID>
__global__ void __launch_bounds__(256, 1) kMMA(const __nv_bfloat16* __restrict__ Ag,
                                               const __nv_bfloat16* __restrict__ Bg,
                                               float* __restrict__ Cg,
                                               const float* __restrict__ Rg,
                                               int Mb, int Nb, int ldc) {
    extern __shared__ char smem[];
    constexpr int NCH = KTOT / 64;
    const int tid = threadIdx.x, wid = tid >> 5, lane = tid & 31;
    const int wm = wid & 3, wn = wid >> 2;           // warp grid 4 (m) x 2 (n)
    const int b = blockIdx.z, m0 = blockIdx.y * 128, n0 = blockIdx.x * 128;
    const __nv_bfloat16* Arow = Ag + ((size_t)b * Mb + m0) * KTOT;
    const __nv_bfloat16* Brow = Bg + ((size_t)b * Nb + n0) * KTOT;

    float acc[2][8][4] = {};                          // [mi][nf][reg]

    // chunk load via cp.async: 128 rows x 64 bf16 (=128B) per operand
    auto load_chunk = [&](int c, int buf) {
        int k0 = c * 64;
        char* sA = smem + buf * 32768;
        char* sB = smem + buf * 32768 + 16384;
        #pragma unroll
        for (int i = 0; i < 4; i++) {
            int idx = i * 256 + tid;                  // 0..1023
            int r = idx >> 3, cc = idx & 7;
            uint32_t off = sw128((uint32_t)(r * 128 + cc * 16));
            uint32_t dA = smem_u32(sA + off);
            const __nv_bfloat16* srcA = Arow + (size_t)r * KTOT + k0 + cc * 8;
            asm volatile("cp.async.cg.shared.global [%0], [%1], 16;" :: "r"(dA), "l"(srcA));
            uint32_t dB = smem_u32(sB + off);
            const __nv_bfloat16* srcB = Brow + (size_t)r * KTOT + k0 + cc * 8;
            asm volatile("cp.async.cg.shared.global [%0], [%1], 16;" :: "r"(dB), "l"(srcB));
        }
        asm volatile("cp.async.commit_group;" ::: "memory");
    };

    load_chunk(0, 0);
    for (int c = 0; c < NCH; c++) {
        int buf = c & 1;
        if (c + 1 < NCH) {
            load_chunk(c + 1, buf ^ 1);
            asm volatile("cp.async.wait_group 1;" ::: "memory");
        } else {
            asm volatile("cp.async.wait_group 0;" ::: "memory");
        }
        __syncthreads();
        const char* sA = smem + buf * 32768;
        const char* sB = smem + buf * 32768 + 16384;
        #pragma unroll
        for (int ks = 0; ks < 4; ks++) {
            const int kk = ks * 16;
            uint32_t af[2][4], bf[4][4];
            #pragma unroll
            for (int mi = 0; mi < 2; mi++) {
                int row = wm * 32 + mi * 16 + (lane & 15);
                int col = kk + ((lane >> 4) << 3);
                uint32_t addr = smem_u32(sA + sw128((uint32_t)(row * 128 + col * 2)));
                asm volatile("ldmatrix.sync.aligned.m8n8.x4.shared.b16 {%0,%1,%2,%3}, [%4];"
                    : "=r"(af[mi][0]), "=r"(af[mi][1]), "=r"(af[mi][2]), "=r"(af[mi][3])
                    : "r"(addr));
            }
            #pragma unroll
            for (int nj = 0; nj < 4; nj++) {
                // matrices: [n0-7,k0-7], [n0-7,k8-15], [n8-15,k0-7], [n8-15,k8-15]
                int nr = wn * 64 + nj * 16 + ((lane >> 4) << 3) + (lane & 7);
                int kc = kk + (((lane >> 3) & 1) << 3);
                uint32_t addr = smem_u32(sB + sw128((uint32_t)(nr * 128 + kc * 2)));
                asm volatile("ldmatrix.sync.aligned.m8n8.x4.shared.b16 {%0,%1,%2,%3}, [%4];"
                    : "=r"(bf[nj][0]), "=r"(bf[nj][1]), "=r"(bf[nj][2]), "=r"(bf[nj][3])
                    : "r"(addr));
            }
            #pragma unroll
            for (int mi = 0; mi < 2; mi++) {
                #pragma unroll
                for (int nj = 0; nj < 4; nj++) {
                    float* c0 = acc[mi][nj * 2];
                    asm volatile(
                        "mma.sync.aligned.m16n8k16.row.col.f32.bf16.bf16.f32 "
                        "{%0,%1,%2,%3}, {%4,%5,%6,%7}, {%8,%9}, {%0,%1,%2,%3};"
                        : "+f"(c0[0]), "+f"(c0[1]), "+f"(c0[2]), "+f"(c0[3])
                        : "r"(af[mi][0]), "r"(af[mi][1]), "r"(af[mi][2]), "r"(af[mi][3]),
                          "r"(bf[nj][0]), "r"(bf[nj][1]));
                    float* c1 = acc[mi][nj * 2 + 1];
                    asm volatile(
                        "mma.sync.aligned.m16n8k16.row.col.f32.bf16.bf16.f32 "
                        "{%0,%1,%2,%3}, {%4,%5,%6,%7}, {%8,%9}, {%0,%1,%2,%3};"
                        : "+f"(c1[0]), "+f"(c1[1]), "+f"(c1[2]), "+f"(c1[3])
                        : "r"(af[mi][0]), "r"(af[mi][1]), "r"(af[mi][2]), "r"(af[mi][3]),
                          "r"(bf[nj][2]), "r"(bf[nj][3]));
                }
            }
        }
        __syncthreads();
    }

    // Epilogue: C frag m16n8 -> thread holds (row lane/4, cols (lane%4)*2..+1) and (+8 row)
    #pragma unroll
    for (int mi = 0; mi < 2; mi++) {
        int row = m0 + wm * 32 + mi * 16 + (lane >> 2);
        size_t base = ((size_t)b * Mb + row) * ldc + n0 + wn * 64 + (lane & 3) * 2;
        #pragma unroll
        for (int nf = 0; nf < 8; nf++) {
            size_t o = base + nf * 8;
            float2 v0 = make_float2(acc[mi][nf][0], acc[mi][nf][1]);
            float2 v1 = make_float2(acc[mi][nf][2], acc[mi][nf][3]);
            if (RESID) {
                float2 r0 = *(const float2*)(Rg + o);
                float2 r1 = *(const float2*)(Rg + o + 8 * (size_t)ldc);
                v0.x += r0.x; v0.y += r0.y;
                v1.x += r1.x; v1.y += r1.y;
            }
            *(float2*)(Cg + o) = v0;
            *(float2*)(Cg + o + 8 * (size_t)ldc) = v1;
        }
    }
}

// softmax over rows of g_sc, writes split-bf16 Pcat: [hi, hi, lo]
__global__ void __launch_bounds__(256) kSoftmax() {
    __shared__ float red[256];
    size_t row = blockIdx.x;
    const float* r = g_sc + row * S_;
    __nv_bfloat16* pc = g_pcat + row * KPV;
    float vals[8];
    float mx = -1e30f;
    #pragma unroll
    for (int i = 0; i < 8; i++) {
        vals[i] = r[threadIdx.x + i * 256];
        mx = fmaxf(mx, vals[i]);
    }
    red[threadIdx.x] = mx;
    __syncthreads();
    for (int off = 128; off > 0; off >>= 1) {
        if (threadIdx.x < off)
            red[threadIdx.x] = fmaxf(red[threadIdx.x], red[threadIdx.x + off]);
        __syncthreads();
    }
    mx = red[0];
    __syncthreads();
    float sum = 0.0f;
    #pragma unroll
    for (int i = 0; i < 8; i++) {
        vals[i] = __expf(vals[i] - mx);
        sum += vals[i];
    }
    red[threadIdx.x] = sum;
    __syncthreads();
    for (int off = 128; off > 0; off >>= 1) {
        if (threadIdx.x < off) red[threadIdx.x] += red[threadIdx.x + off];
        __syncthreads();
    }
    float inv = 1.0f / red[0];
    #pragma unroll
    for (int i = 0; i < 8; i++) {
        int t = threadIdx.x + i * 256;
        float p = vals[i] * inv;
        __nv_bfloat16 h = __float2bfloat16(p);
        __nv_bfloat16 l = __float2bfloat16(p - __bfloat162float(h));
        pc[t] = h; pc[S_ + t] = h; pc[2 * S_ + t] = l;
    }
}

// ---------------- Block C: FFN ----------------
__global__ void __launch_bounds__(256) kC(const float* __restrict__ alpha,
                                          const float* __restrict__ w,
                                          const float* __restrict__ bia,
                                          const float* __restrict__ br,
                                          const float* __restrict__ bi,
                                          float* __restrict__ out) {
    __shared__ float2 s0[D_], s1[D_], tw[D_ / 2];
    size_t row = blockIdx.x;
    float al = alpha[0];
    for (int i = threadIdx.x; i < D_ / 2; i += 256) tw[i] = g_twD[i];
    for (int d = threadIdx.x; d < D_; d += 256)
        s0[d] = make_float2(tanhf(al * g_x2[row * D_ + d]) * w[d] + bia[d], 0.0f);
    float2* res = block_fft<D_, 256, false>(s0, s1, tw);
    for (int d = threadIdx.x; d < D_; d += 256)
        res[d] = cmul(res[d], make_float2(br[d], bi[d]));
    float2* other = (res == s0) ? s1 : s0;
    float2* r2 = block_fft<D_, 256, true>(res, other, tw);
    const float sc = 1.0f / (float)D_;
    for (int d = threadIdx.x; d < D_; d += 256)
        out[row * D_ + d] = r2[d].x * sc + g_x2[row * D_ + d];
}

// ---------------- launch ----------------
extern "C" void kernel_launch(void* const* d_in, const int* in_sizes, int n_in,
                              void* d_out, int out_size) {
    (void)n_in; (void)out_size;

    const float* x;
    const float *a_qr, *a_qi, *a_kr, *a_ki, *a_vr, *a_vi, *a_rtr, *a_rti;
    const float *b_qr, *b_qi, *b_kr, *b_ki, *b_vr, *b_vi;
    const float *f_br, *f_bi;
    const float *dyta_al, *dyta_w, *dyta_b;
    const float *dytb_al, *dytb_w, *dytb_b;
    const float *dytf_al, *dytf_w, *dytf_b;

    bool sig_order = (in_sizes[9] == 1);
    x = (const float*)d_in[0];
    if (sig_order) {
        a_qr   = (const float*)d_in[1];  a_qi   = (const float*)d_in[2];
        a_kr   = (const float*)d_in[3];  a_ki   = (const float*)d_in[4];
        a_vr   = (const float*)d_in[5];  a_vi   = (const float*)d_in[6];
        a_rtr  = (const float*)d_in[7];  a_rti  = (const float*)d_in[8];
        dyta_al= (const float*)d_in[9];  dyta_w = (const float*)d_in[10]; dyta_b = (const float*)d_in[11];
        b_qr   = (const float*)d_in[12]; b_qi   = (const float*)d_in[13];
        b_kr   = (const float*)d_in[14]; b_ki   = (const float*)d_in[15];
        b_vr   = (const float*)d_in[16]; b_vi   = (const float*)d_in[17];
        dytb_al= (const float*)d_in[18]; dytb_w = (const float*)d_in[19]; dytb_b = (const float*)d_in[20];
        f_br   = (const float*)d_in[23]; f_bi   = (const float*)d_in[24];
        dytf_al= (const float*)d_in[26]; dytf_w = (const float*)d_in[27]; dytf_b = (const float*)d_in[28];
    } else {
        a_qr   = (const float*)d_in[1];  a_kr   = (const float*)d_in[2];
        a_vr   = (const float*)d_in[3];  a_rtr  = (const float*)d_in[4];
        b_qr   = (const float*)d_in[5];  b_kr   = (const float*)d_in[6];
        b_vr   = (const float*)d_in[7];
        f_br   = (const float*)d_in[9];
        a_qi   = (const float*)d_in[10]; a_ki   = (const float*)d_in[11];
        a_vi   = (const float*)d_in[12]; a_rti  = (const float*)d_in[13];
        b_qi   = (const float*)d_in[14]; b_ki   = (const float*)d_in[15];
        b_vi   = (const float*)d_in[16];
        f_bi   = (const float*)d_in[18];
        dyta_al= (const float*)d_in[20]; dyta_w = (const float*)d_in[21]; dyta_b = (const float*)d_in[22];
        dytb_al= (const float*)d_in[23]; dytb_w = (const float*)d_in[24]; dytb_b = (const float*)d_in[25];
        dytf_al= (const float*)d_in[26]; dytf_w = (const float*)d_in[27]; dytf_b = (const float*)d_in[28];
    }
    float* out = (float*)d_out;

    constexpr int GEMM_SMEM = 2 * 32768;   // 64 KB (double-buffered A+B)
    cudaFuncSetAttribute(kMMA<KQK, false>, cudaFuncAttributeMaxDynamicSharedMemorySize, GEMM_SMEM);
    cudaFuncSetAttribute(kMMA<KPV, true>,  cudaFuncAttributeMaxDynamicSharedMemorySize, GEMM_SMEM);

    float* g_sc_p;   cudaGetSymbolAddress((void**)&g_sc_p, g_sc);
    float* g_x1_p;   cudaGetSymbolAddress((void**)&g_x1_p, g_x1);
    float* g_x2_p;   cudaGetSymbolAddress((void**)&g_x2_p, g_x2);
    __nv_bfloat16 *qc_p, *kc_p, *vt_p, *pc_p;
    cudaGetSymbolAddress((void**)&qc_p, g_qcat);
    cudaGetSymbolAddress((void**)&kc_p, g_kcat);
    cudaGetSymbolAddress((void**)&vt_p, g_vt);
    cudaGetSymbolAddress((void**)&pc_p, g_pcat);

    kInit<<<4, 256>>>();
    // Block A
    kA1<<<B_ * S_, 256>>>(x, dyta_al, dyta_w, dyta_b);
    kA2<<<B_ * D_, 256>>>(a_qr, a_qi, a_kr, a_ki, a_vr, a_vi, a_rtr, a_rti);
    kA3<<<B_ * S_, 256>>>(x);
    // Block B
    kB1<<<B_ * S_, 256>>>(dytb_al, dytb_w, dytb_b, b_qr, b_qi, b_kr, b_ki, b_vr, b_vi);
    kVT<<<dim3(D_ / 32, S_ / 32, B_), 256>>>();
    // QK^T -> scores (scale folded into qcat)
    kMMA<KQK, false><<<dim3(S_ / 128, S_ / 128, B_), 256, GEMM_SMEM>>>(
        qc_p, kc_p, g_sc_p, nullptr, S_, S_, S_);
    kSoftmax<<<B_ * S_, 256>>>();
    // P·V + x1 -> x2
    kMMA<KPV, true><<<dim3(D_ / 128, S_ / 128, B_), 256, GEMM_SMEM>>>(
        pc_p, vt_p, g_x2_p, g_x1_p, S_, D_, D_);
    // Block C
    kC<<<B_ * S_, 256>>>(dytf_al, dytf_w, dytf_b, f_br, f_bi, out);
}